// round 14
// baseline (speedup 1.0000x reference)
#include <cuda_runtime.h>
#include <cuda_bf16.h>
#include <cstdint>

// Problem constants
#define S_LEN   4096
#define DMODEL  1024
#define NHEAD   16
#define HDIM    64
#define N3      3072

// Scratch (__device__ globals per allocation-free rule)
__device__ float g_qkv[S_LEN * N3];
__device__ float g_attn[S_LEN * DMODEL];
__device__ float g_wqt[N3 * DMODEL];      // w_qkv^T fp32
__device__ float g_wpt[DMODEL * DMODEL];  // w_proj^T fp32
__device__ __nv_bfloat16 g_qkvh[S_LEN * N3], g_qkvl[S_LEN * N3];

// ---------------------------------------------------------------------------
// PTX helpers
// ---------------------------------------------------------------------------
__device__ __forceinline__ uint32_t smem_u32(const void* p) {
    uint32_t a;
    asm("{ .reg .u64 t; cvta.to.shared.u64 t, %1; cvt.u32.u64 %0, t; }"
        : "=r"(a) : "l"(p));
    return a;
}

__device__ __forceinline__ void mma_bf16(float* c, const uint32_t* a, const uint32_t* b) {
    asm volatile(
        "mma.sync.aligned.m16n8k16.row.col.f32.bf16.bf16.f32 "
        "{%0,%1,%2,%3}, {%4,%5,%6,%7}, {%8,%9}, {%0,%1,%2,%3};"
        : "+f"(c[0]), "+f"(c[1]), "+f"(c[2]), "+f"(c[3])
        : "r"(a[0]), "r"(a[1]), "r"(a[2]), "r"(a[3]), "r"(b[0]), "r"(b[1]));
}

__device__ __forceinline__ void mma_tf32(float* c, const uint32_t* a, const uint32_t* b) {
    asm volatile(
        "mma.sync.aligned.m16n8k8.row.col.f32.tf32.tf32.f32 "
        "{%0,%1,%2,%3}, {%4,%5,%6,%7}, {%8,%9}, {%0,%1,%2,%3};"
        : "+f"(c[0]), "+f"(c[1]), "+f"(c[2]), "+f"(c[3])
        : "r"(a[0]), "r"(a[1]), "r"(a[2]), "r"(a[3]), "r"(b[0]), "r"(b[1]));
}

__device__ __forceinline__ uint32_t f2tf32(float x) {
    uint32_t r;
    asm("cvt.rna.tf32.f32 %0, %1;" : "=r"(r) : "f"(x));
    return r;
}

__device__ __forceinline__ void ldm_x4(uint32_t* r, uint32_t saddr) {
    asm volatile("ldmatrix.sync.aligned.m8n8.x4.shared.b16 {%0,%1,%2,%3}, [%4];"
                 : "=r"(r[0]), "=r"(r[1]), "=r"(r[2]), "=r"(r[3]) : "r"(saddr));
}
__device__ __forceinline__ void ldm_x4_t(uint32_t* r, uint32_t saddr) {
    asm volatile("ldmatrix.sync.aligned.m8n8.x4.trans.shared.b16 {%0,%1,%2,%3}, [%4];"
                 : "=r"(r[0]), "=r"(r[1]), "=r"(r[2]), "=r"(r[3]) : "r"(saddr));
}

// pack two fp32 into bf16x2 hi + residual lo
__device__ __forceinline__ void pack_pair(float p0, float p1, uint32_t& hi, uint32_t& lo) {
    __nv_bfloat162 h;
    h.x = __float2bfloat16(p0);
    h.y = __float2bfloat16(p1);
    hi = *reinterpret_cast<uint32_t*>(&h);
    __nv_bfloat162 l;
    l.x = __float2bfloat16(p0 - __bfloat162float(h.x));
    l.y = __float2bfloat16(p1 - __bfloat162float(h.y));
    lo = *reinterpret_cast<uint32_t*>(&l);
}

// split fp32x4 -> hi/lo bf16x2 pairs at base+idx (idx multiple of 4)
__device__ __forceinline__ void split_store4(__nv_bfloat16* bh, __nv_bfloat16* bl,
                                             int idx, float4 v) {
    __nv_bfloat162 h0; h0.x = __float2bfloat16(v.x); h0.y = __float2bfloat16(v.y);
    __nv_bfloat162 h1; h1.x = __float2bfloat16(v.z); h1.y = __float2bfloat16(v.w);
    __nv_bfloat162 l0;
    l0.x = __float2bfloat16(v.x - __bfloat162float(h0.x));
    l0.y = __float2bfloat16(v.y - __bfloat162float(h0.y));
    __nv_bfloat162 l1;
    l1.x = __float2bfloat16(v.z - __bfloat162float(h1.x));
    l1.y = __float2bfloat16(v.w - __bfloat162float(h1.y));
    *reinterpret_cast<__nv_bfloat162*>(bh + idx)     = h0;
    *reinterpret_cast<__nv_bfloat162*>(bh + idx + 2) = h1;
    *reinterpret_cast<__nv_bfloat162*>(bl + idx)     = l0;
    *reinterpret_cast<__nv_bfloat162*>(bl + idx + 2) = l1;
}

// ---------------------------------------------------------------------------
// Prep: split fp32 -> bf16 hi/lo (flash inputs)
// ---------------------------------------------------------------------------
__global__ void __launch_bounds__(256)
split_kernel(const float* __restrict__ in,
             __nv_bfloat16* __restrict__ hi, __nv_bfloat16* __restrict__ lo) {
    int i = (blockIdx.x * 256 + threadIdx.x) * 4;
    float4 v = *reinterpret_cast<const float4*>(in + i);
    split_store4(hi, lo, i, v);
}

// Prep: W [Kd][Nd] fp32 -> W^T [Nd][Kd] fp32
__global__ void __launch_bounds__(256)
transposeT_kernel(const float* __restrict__ W, float* __restrict__ WT,
                  int Kd, int Nd) {
    __shared__ float tl[32][33];
    int n0 = blockIdx.x * 32, k0 = blockIdx.y * 32;
    int tx = threadIdx.x, ty = threadIdx.y;
    #pragma unroll
    for (int j = 0; j < 4; j++)
        tl[ty + 8 * j][tx] = W[(size_t)(k0 + ty + 8 * j) * Nd + n0 + tx];
    __syncthreads();
    #pragma unroll
    for (int j = 0; j < 4; j++)
        WT[(size_t)(n0 + ty + 8 * j) * Kd + k0 + tx] = tl[tx][ty + 8 * j];
}

// ---------------------------------------------------------------------------
// tf32 GEMM on HMMA: C[M,N] = A @ B^T + bias.
// A [M][K] fp32, BT [N][K] fp32. CTA 128x128, K-chunk 32, 8 warps (2m x 4n).
// Fragments via scalar LDS (R5-validated tf32 pattern); cvt.rna at smem store.
// Stride 36 floats: (4g+q4)%32 all-distinct -> conflict-free fragment loads.
// ---------------------------------------------------------------------------
#define TS_LD 36
__global__ void __launch_bounds__(256, 2)
gemm_tf32_kernel(const float* __restrict__ A, const float* __restrict__ BT,
                 const float* __restrict__ bias, float* __restrict__ C,
                 int M, int N, int K) {
    __shared__ uint32_t As[128 * TS_LD];
    __shared__ uint32_t Bs[128 * TS_LD];

    const int tid = threadIdx.x;
    const int wid = tid >> 5, lane = tid & 31;
    const int g = lane >> 2, q4 = lane & 3;
    const int wm = wid >> 2, wn = wid & 3;
    const int m0 = blockIdx.y * 128, n0 = blockIdx.x * 128;
    const int lrow = tid >> 1, lcol = (tid & 1) * 16;

    const float* pA = A + (size_t)(m0 + lrow) * K + lcol;
    const float* pB = BT + (size_t)(n0 + lrow) * K + lcol;
    uint32_t* sa = As + lrow * TS_LD + lcol;
    uint32_t* sbp = Bs + lrow * TS_LD + lcol;

    float Cf[4][4][4];
    #pragma unroll
    for (int mt = 0; mt < 4; mt++)
        #pragma unroll
        for (int nt = 0; nt < 4; nt++)
            #pragma unroll
            for (int e = 0; e < 4; e++) Cf[mt][nt][e] = 0.0f;

    const uint32_t* Aw = As + (wm * 64) * TS_LD;
    const uint32_t* Bw = Bs + (wn * 32) * TS_LD;

    for (int k0 = 0; k0 < K; k0 += 32) {
        // batched loads before barrier (MLP=8)
        float4 ra[4], rb[4];
        #pragma unroll
        for (int i = 0; i < 4; i++) {
            ra[i] = *reinterpret_cast<const float4*>(pA + k0 + i * 4);
            rb[i] = *reinterpret_cast<const float4*>(pB + k0 + i * 4);
        }
        __syncthreads();
        #pragma unroll
        for (int i = 0; i < 4; i++) {
            sa[i * 4 + 0] = f2tf32(ra[i].x);
            sa[i * 4 + 1] = f2tf32(ra[i].y);
            sa[i * 4 + 2] = f2tf32(ra[i].z);
            sa[i * 4 + 3] = f2tf32(ra[i].w);
            sbp[i * 4 + 0] = f2tf32(rb[i].x);
            sbp[i * 4 + 1] = f2tf32(rb[i].y);
            sbp[i * 4 + 2] = f2tf32(rb[i].z);
            sbp[i * 4 + 3] = f2tf32(rb[i].w);
        }
        __syncthreads();

        #pragma unroll
        for (int ks = 0; ks < 4; ks++) {
            const int kk = ks * 8 + q4;
            uint32_t bf[4][2];
            #pragma unroll
            for (int nt = 0; nt < 4; nt++) {
                bf[nt][0] = Bw[(nt * 8 + g) * TS_LD + kk];
                bf[nt][1] = Bw[(nt * 8 + g) * TS_LD + kk + 4];
            }
            #pragma unroll
            for (int mt = 0; mt < 4; mt++) {
                uint32_t a[4];
                a[0] = Aw[(mt * 16 + g) * TS_LD + kk];
                a[1] = Aw[(mt * 16 + 8 + g) * TS_LD + kk];
                a[2] = Aw[(mt * 16 + g) * TS_LD + kk + 4];
                a[3] = Aw[(mt * 16 + 8 + g) * TS_LD + kk + 4];
                mma_tf32(Cf[mt][0], a, bf[0]);
                mma_tf32(Cf[mt][1], a, bf[1]);
                mma_tf32(Cf[mt][2], a, bf[2]);
                mma_tf32(Cf[mt][3], a, bf[3]);
            }
        }
    }

    #pragma unroll
    for (int mt = 0; mt < 4; mt++) {
        int row = m0 + wm * 64 + mt * 16 + g;
        #pragma unroll
        for (int nt = 0; nt < 4; nt++) {
            int col = n0 + wn * 32 + nt * 8 + 2 * q4;
            float2 b2 = *reinterpret_cast<const float2*>(bias + col);
            float2 o0 = {Cf[mt][nt][0] + b2.x, Cf[mt][nt][1] + b2.y};
            float2 o1 = {Cf[mt][nt][2] + b2.x, Cf[mt][nt][3] + b2.y};
            *reinterpret_cast<float2*>(C + (size_t)row * N + col) = o0;
            *reinterpret_cast<float2*>(C + (size_t)(row + 8) * N + col) = o1;
        }
    }
}

// ---------------------------------------------------------------------------
// Flash attention, bf16-split HMMA + ldmatrix (R13 verbatim — validated).
// ---------------------------------------------------------------------------
#define FLD 72
#define OQH 0
#define OQL (128 * FLD)
#define OKH (2 * 128 * FLD)
#define OKL (OKH + 64 * FLD)
#define OVH (OKL + 64 * FLD)
#define OVL (OVH + 64 * FLD)
#define FLASH_SMEM ((OVL + 64 * FLD) * 2)   // 73728 B

__global__ void __launch_bounds__(256, 2)
flash_bf16_kernel(const __nv_bfloat16* __restrict__ qh_g,
                  const __nv_bfloat16* __restrict__ ql_g,
                  float* __restrict__ outp) {
    extern __shared__ __nv_bfloat16 smf[];
    const uint32_t sb = smem_u32(smf);

    const int qb = (S_LEN / 128 - 1) - blockIdx.x;   // heavy tiles first
    const int h  = blockIdx.y;
    const int tid = threadIdx.x;
    const int wid = tid >> 5, lane = tid & 31;
    const int g = lane >> 2, q4 = lane & 3;
    const int qcol = h * HDIM;
    const float scale = 0.125f;

    const uint32_t qoff2 = (uint32_t)(((wid * 16) + ((lane >> 3) & 1) * 8 + (lane & 7)) * FLD
                                      + (lane >> 4) * 8) * 2;
    const uint32_t koff2 = (uint32_t)(((lane >> 4) * 8 + (lane & 7)) * FLD
                                      + ((lane >> 3) & 1) * 8) * 2;
    const uint32_t voff2 = (uint32_t)((((lane >> 3) & 1) * 8 + (lane & 7)) * FLD
                                      + (lane >> 4) * 8) * 2;

    #pragma unroll
    for (int i = 0; i < 4; i++) {
        int p = tid + i * 256;
        int r = p >> 3, c8 = (p & 7) * 8;
        size_t src = (size_t)(qb * 128 + r) * N3 + qcol + c8;
        *reinterpret_cast<uint4*>(&smf[OQH + r * FLD + c8]) =
            *reinterpret_cast<const uint4*>(qh_g + src);
        *reinterpret_cast<uint4*>(&smf[OQL + r * FLD + c8]) =
            *reinterpret_cast<const uint4*>(ql_g + src);
    }

    float O[8][4];
    #pragma unroll
    for (int nt = 0; nt < 8; nt++)
        #pragma unroll
        for (int e = 0; e < 4; e++) O[nt][e] = 0.0f;
    float m0r = -1e30f, m1r = -1e30f, l0r = 0.0f, l1r = 0.0f;

    const uint32_t qbh = sb + OQH * 2 + qoff2;
    const uint32_t qbl = sb + OQL * 2 + qoff2;
    const uint32_t kbh = sb + OKH * 2 + koff2;
    const uint32_t kbl = sb + OKL * 2 + koff2;
    const uint32_t vbh = sb + OVH * 2 + voff2;
    const uint32_t vbl = sb + OVL * 2 + voff2;

    const int r0_ = tid >> 3, c80_ = (tid & 7) * 8;
    const int r1_ = (tid + 256) >> 3, c81_ = ((tid + 256) & 7) * 8;

    const int nkt = 2 * qb + 2;
    for (int kb = 0; kb < nkt; kb++) {
        size_t ks0 = (size_t)(kb * 64 + r0_) * N3 + DMODEL + qcol + c80_;
        size_t ks1 = (size_t)(kb * 64 + r1_) * N3 + DMODEL + qcol + c81_;
        uint4 kh0 = *reinterpret_cast<const uint4*>(qh_g + ks0);
        uint4 kl0 = *reinterpret_cast<const uint4*>(ql_g + ks0);
        uint4 vh0 = *reinterpret_cast<const uint4*>(qh_g + ks0 + DMODEL);
        uint4 vl0 = *reinterpret_cast<const uint4*>(ql_g + ks0 + DMODEL);
        uint4 kh1 = *reinterpret_cast<const uint4*>(qh_g + ks1);
        uint4 kl1 = *reinterpret_cast<const uint4*>(ql_g + ks1);
        uint4 vh1 = *reinterpret_cast<const uint4*>(qh_g + ks1 + DMODEL);
        uint4 vl1 = *reinterpret_cast<const uint4*>(ql_g + ks1 + DMODEL);
        __syncthreads();
        *reinterpret_cast<uint4*>(&smf[OKH + r0_ * FLD + c80_]) = kh0;
        *reinterpret_cast<uint4*>(&smf[OKL + r0_ * FLD + c80_]) = kl0;
        *reinterpret_cast<uint4*>(&smf[OVH + r0_ * FLD + c80_]) = vh0;
        *reinterpret_cast<uint4*>(&smf[OVL + r0_ * FLD + c80_]) = vl0;
        *reinterpret_cast<uint4*>(&smf[OKH + r1_ * FLD + c81_]) = kh1;
        *reinterpret_cast<uint4*>(&smf[OKL + r1_ * FLD + c81_]) = kl1;
        *reinterpret_cast<uint4*>(&smf[OVH + r1_ * FLD + c81_]) = vh1;
        *reinterpret_cast<uint4*>(&smf[OVL + r1_ * FLD + c81_]) = vl1;
        __syncthreads();

        float S[8][4];
        #pragma unroll
        for (int nt = 0; nt < 8; nt++)
            #pragma unroll
            for (int e = 0; e < 4; e++) S[nt][e] = 0.0f;

        #pragma unroll
        for (int ks = 0; ks < 4; ks++) {
            uint32_t qh4[4], ql4[4];
            ldm_x4(qh4, qbh + ks * 32);
            ldm_x4(ql4, qbl + ks * 32);
            #pragma unroll
            for (int ntp = 0; ntp < 4; ntp++) {
                uint32_t kh4[4], kl4[4];
                ldm_x4(kh4, kbh + ntp * 2304 + ks * 32);
                ldm_x4(kl4, kbl + ntp * 2304 + ks * 32);
                mma_bf16(S[2 * ntp],     qh4, &kh4[0]);
                mma_bf16(S[2 * ntp + 1], qh4, &kh4[2]);
                mma_bf16(S[2 * ntp],     qh4, &kl4[0]);
                mma_bf16(S[2 * ntp + 1], qh4, &kl4[2]);
                mma_bf16(S[2 * ntp],     ql4, &kh4[0]);
                mma_bf16(S[2 * ntp + 1], ql4, &kh4[2]);
            }
        }

        #pragma unroll
        for (int nt = 0; nt < 8; nt++) {
            S[nt][0] *= scale; S[nt][1] *= scale;
            S[nt][2] *= scale; S[nt][3] *= scale;
        }
        if (kb >= 2 * qb) {
            int row0 = qb * 128 + wid * 16 + g;
            int row1 = row0 + 8;
            #pragma unroll
            for (int nt = 0; nt < 8; nt++) {
                int c = kb * 64 + nt * 8 + 2 * q4;
                if (c     > row0) S[nt][0] = -1e30f;
                if (c + 1 > row0) S[nt][1] = -1e30f;
                if (c     > row1) S[nt][2] = -1e30f;
                if (c + 1 > row1) S[nt][3] = -1e30f;
            }
        }

        float mx0 = -1e30f, mx1 = -1e30f;
        #pragma unroll
        for (int nt = 0; nt < 8; nt++) {
            mx0 = fmaxf(mx0, fmaxf(S[nt][0], S[nt][1]));
            mx1 = fmaxf(mx1, fmaxf(S[nt][2], S[nt][3]));
        }
        mx0 = fmaxf(mx0, __shfl_xor_sync(0xffffffffu, mx0, 1));
        mx0 = fmaxf(mx0, __shfl_xor_sync(0xffffffffu, mx0, 2));
        mx1 = fmaxf(mx1, __shfl_xor_sync(0xffffffffu, mx1, 1));
        mx1 = fmaxf(mx1, __shfl_xor_sync(0xffffffffu, mx1, 2));
        float mn0 = fmaxf(m0r, mx0), mn1 = fmaxf(m1r, mx1);
        float al0 = __expf(m0r - mn0), al1 = __expf(m1r - mn1);
        float rs0 = 0.0f, rs1 = 0.0f;
        #pragma unroll
        for (int nt = 0; nt < 8; nt++) {
            S[nt][0] = __expf(S[nt][0] - mn0);
            S[nt][1] = __expf(S[nt][1] - mn0);
            S[nt][2] = __expf(S[nt][2] - mn1);
            S[nt][3] = __expf(S[nt][3] - mn1);
            rs0 += S[nt][0] + S[nt][1];
            rs1 += S[nt][2] + S[nt][3];
        }
        rs0 += __shfl_xor_sync(0xffffffffu, rs0, 1);
        rs0 += __shfl_xor_sync(0xffffffffu, rs0, 2);
        rs1 += __shfl_xor_sync(0xffffffffu, rs1, 1);
        rs1 += __shfl_xor_sync(0xffffffffu, rs1, 2);
        l0r = l0r * al0 + rs0;
        l1r = l1r * al1 + rs1;
        m0r = mn0; m1r = mn1;
        #pragma unroll
        for (int nt = 0; nt < 8; nt++) {
            O[nt][0] *= al0; O[nt][1] *= al0;
            O[nt][2] *= al1; O[nt][3] *= al1;
        }

        #pragma unroll
        for (int ks = 0; ks < 4; ks++) {
            uint32_t ph[4], pl[4];
            pack_pair(S[2 * ks][0],     S[2 * ks][1],     ph[0], pl[0]);
            pack_pair(S[2 * ks][2],     S[2 * ks][3],     ph[1], pl[1]);
            pack_pair(S[2 * ks + 1][0], S[2 * ks + 1][1], ph[2], pl[2]);
            pack_pair(S[2 * ks + 1][2], S[2 * ks + 1][3], ph[3], pl[3]);
            #pragma unroll
            for (int ntp = 0; ntp < 4; ntp++) {
                uint32_t vh4[4], vl4[4];
                ldm_x4_t(vh4, vbh + ks * 2304 + ntp * 32);
                ldm_x4_t(vl4, vbl + ks * 2304 + ntp * 32);
                mma_bf16(O[2 * ntp],     ph, &vh4[0]);
                mma_bf16(O[2 * ntp + 1], ph, &vh4[2]);
                mma_bf16(O[2 * ntp],     ph, &vl4[0]);
                mma_bf16(O[2 * ntp + 1], ph, &vl4[2]);
                mma_bf16(O[2 * ntp],     pl, &vh4[0]);
                mma_bf16(O[2 * ntp + 1], pl, &vh4[2]);
            }
        }
    }

    float inv0 = 1.0f / l0r, inv1 = 1.0f / l1r;
    int row0 = qb * 128 + wid * 16 + g;
    int row1 = row0 + 8;
    #pragma unroll
    for (int nt = 0; nt < 8; nt++) {
        int col = qcol + nt * 8 + 2 * q4;
        float2 o0 = {O[nt][0] * inv0, O[nt][1] * inv0};
        float2 o1 = {O[nt][2] * inv1, O[nt][3] * inv1};
        *reinterpret_cast<float2*>(outp + (size_t)row0 * DMODEL + col) = o0;
        *reinterpret_cast<float2*>(outp + (size_t)row1 * DMODEL + col) = o1;
    }
}

// ---------------------------------------------------------------------------
// Launch
// ---------------------------------------------------------------------------
extern "C" void kernel_launch(void* const* d_in, const int* in_sizes, int n_in,
                              void* d_out, int out_size) {
    const float* x      = (const float*)d_in[0];
    const float* w_qkv  = (const float*)d_in[1];
    const float* b_qkv  = (const float*)d_in[2];
    const float* w_proj = (const float*)d_in[3];
    const float* b_proj = (const float*)d_in[4];
    float* out = (float*)d_out;

    float *qkv, *attn, *wqt, *wpt;
    __nv_bfloat16 *qkvh, *qkvl;
    cudaGetSymbolAddress((void**)&qkv, g_qkv);
    cudaGetSymbolAddress((void**)&attn, g_attn);
    cudaGetSymbolAddress((void**)&wqt, g_wqt);
    cudaGetSymbolAddress((void**)&wpt, g_wpt);
    cudaGetSymbolAddress((void**)&qkvh, g_qkvh);
    cudaGetSymbolAddress((void**)&qkvl, g_qkvl);

    cudaFuncSetAttribute(flash_bf16_kernel,
                         cudaFuncAttributeMaxDynamicSharedMemorySize, FLASH_SMEM);

    // Prep: transpose weights (fp32)
    transposeT_kernel<<<dim3(N3 / 32, DMODEL / 32), dim3(32, 8)>>>(w_qkv, wqt, DMODEL, N3);
    transposeT_kernel<<<dim3(DMODEL / 32, DMODEL / 32), dim3(32, 8)>>>(w_proj, wpt, DMODEL, DMODEL);

    // 1) QKV projection (tf32 HMMA, fp32 in/out)
    gemm_tf32_kernel<<<dim3(N3 / 128, S_LEN / 128), 256>>>(
        x, wqt, b_qkv, qkv, S_LEN, N3, DMODEL);

    // 1b) Split qkv to bf16 hi/lo for flash
    split_kernel<<<S_LEN * N3 / 1024, 256>>>(qkv, qkvh, qkvl);

    // 2) Causal flash attention (bf16-split HMMA, unchanged)
    flash_bf16_kernel<<<dim3(S_LEN / 128, NHEAD), 256, FLASH_SMEM>>>(qkvh, qkvl, attn);

    // 3) Output projection (tf32 HMMA)
    gemm_tf32_kernel<<<dim3(DMODEL / 128, S_LEN / 128), 256>>>(
        attn, wpt, b_proj, out, S_LEN, DMODEL, DMODEL);
}

// round 17
// speedup vs baseline: 1.9580x; 1.9580x over previous
#include <cuda_runtime.h>
#include <cuda_fp16.h>
#include <cstdint>

// Problem constants
#define S_LEN   4096
#define DMODEL  1024
#define NHEAD   16
#define HDIM    64
#define N3      3072

// Scratch (__device__ globals per allocation-free rule)
__device__ __half g_xh[S_LEN * DMODEL];
__device__ __half g_wqt[N3 * DMODEL];      // w_qkv^T fp16
__device__ __half g_wpt[DMODEL * DMODEL];  // w_proj^T fp16
__device__ __half g_qkvh[S_LEN * N3];
__device__ __half g_attnh[S_LEN * DMODEL];

// ---------------------------------------------------------------------------
// PTX helpers
// ---------------------------------------------------------------------------
__device__ __forceinline__ uint32_t smem_u32(const void* p) {
    uint32_t a;
    asm("{ .reg .u64 t; cvta.to.shared.u64 t, %1; cvt.u32.u64 %0, t; }"
        : "=r"(a) : "l"(p));
    return a;
}

__device__ __forceinline__ void mma_f16(float* c, const uint32_t* a, const uint32_t* b) {
    asm volatile(
        "mma.sync.aligned.m16n8k16.row.col.f32.f16.f16.f32 "
        "{%0,%1,%2,%3}, {%4,%5,%6,%7}, {%8,%9}, {%0,%1,%2,%3};"
        : "+f"(c[0]), "+f"(c[1]), "+f"(c[2]), "+f"(c[3])
        : "r"(a[0]), "r"(a[1]), "r"(a[2]), "r"(a[3]), "r"(b[0]), "r"(b[1]));
}

__device__ __forceinline__ void ldm_x4(uint32_t* r, uint32_t saddr) {
    asm volatile("ldmatrix.sync.aligned.m8n8.x4.shared.b16 {%0,%1,%2,%3}, [%4];"
                 : "=r"(r[0]), "=r"(r[1]), "=r"(r[2]), "=r"(r[3]) : "r"(saddr));
}
__device__ __forceinline__ void ldm_x4_t(uint32_t* r, uint32_t saddr) {
    asm volatile("ldmatrix.sync.aligned.m8n8.x4.trans.shared.b16 {%0,%1,%2,%3}, [%4];"
                 : "=r"(r[0]), "=r"(r[1]), "=r"(r[2]), "=r"(r[3]) : "r"(saddr));
}

__device__ __forceinline__ uint32_t h2pack(float a, float b) {
    __half2 h = __floats2half2_rn(a, b);
    return *reinterpret_cast<uint32_t*>(&h);
}

// ---------------------------------------------------------------------------
// Prep: fp32 -> fp16 convert (vectorized)
// ---------------------------------------------------------------------------
__global__ void __launch_bounds__(256)
cvt_kernel(const float* __restrict__ in, __half* __restrict__ outp) {
    int i = (blockIdx.x * 256 + threadIdx.x) * 4;
    float4 v = *reinterpret_cast<const float4*>(in + i);
    __half2 h0 = __floats2half2_rn(v.x, v.y);
    __half2 h1 = __floats2half2_rn(v.z, v.w);
    *reinterpret_cast<__half2*>(outp + i)     = h0;
    *reinterpret_cast<__half2*>(outp + i + 2) = h1;
}

// Prep: W [Kd][Nd] fp32 -> W^T [Nd][Kd] fp16
__global__ void __launch_bounds__(256)
transposeT_kernel(const float* __restrict__ W, __half* __restrict__ WT,
                  int Kd, int Nd) {
    __shared__ __half tl[32][33];
    int n0 = blockIdx.x * 32, k0 = blockIdx.y * 32;
    int tx = threadIdx.x, ty = threadIdx.y;
    #pragma unroll
    for (int j = 0; j < 4; j++)
        tl[ty + 8 * j][tx] = __float2half_rn(W[(size_t)(k0 + ty + 8 * j) * Nd + n0 + tx]);
    __syncthreads();
    #pragma unroll
    for (int j = 0; j < 4; j++)
        WT[(size_t)(n0 + ty + 8 * j) * Kd + k0 + tx] = tl[tx][ty + 8 * j];
}

// ---------------------------------------------------------------------------
// fp16 single-pass GEMM on HMMA: C = A @ B^T + bias.
// A [M][K] fp16, BT [N][K] fp16. R8/R13 skeleton: CTA 128x128, K-chunk 32,
// 8 warps (2m x 4n), batched LDG before barrier, ldmatrix fragments.
// Output: fp32 C (proj) or fp16 Ch (qkv), both with bias.
// ---------------------------------------------------------------------------
#define AS_LD 40
__global__ void __launch_bounds__(256, 2)
gemm_f16_kernel(const __half* __restrict__ A, const __half* __restrict__ BT,
                const float* __restrict__ bias, float* __restrict__ C,
                __half* __restrict__ Ch, int M, int N, int K) {
    __shared__ __half Ash[128 * AS_LD];
    __shared__ __half Bsh[128 * AS_LD];

    const int tid = threadIdx.x;
    const int wid = tid >> 5, lane = tid & 31;
    const int g = lane >> 2, q4 = lane & 3;
    const int wm = wid >> 2, wn = wid & 3;
    const int m0 = blockIdx.y * 128, n0 = blockIdx.x * 128;
    const int lrow = tid >> 1, loff = (tid & 1) * 16;

    const uint32_t a_off2 = (uint32_t)(((wm * 64) + ((lane >> 3) & 1) * 8 + (lane & 7)) * AS_LD
                                       + (lane >> 4) * 8) * 2;
    const uint32_t b_off2 = (uint32_t)(((wn * 32) + (lane >> 4) * 8 + (lane & 7)) * AS_LD
                                       + ((lane >> 3) & 1) * 8) * 2;

    const uint32_t sAh = smem_u32(Ash) + a_off2;
    const uint32_t sBh = smem_u32(Bsh) + b_off2;

    const __half* pA = A + (size_t)(m0 + lrow) * K + loff;
    const __half* pB = BT + (size_t)(n0 + lrow) * K + loff;

    float Cf[4][4][4];
    #pragma unroll
    for (int mt = 0; mt < 4; mt++)
        #pragma unroll
        for (int nt = 0; nt < 4; nt++)
            #pragma unroll
            for (int e = 0; e < 4; e++) Cf[mt][nt][e] = 0.0f;

    for (int k0 = 0; k0 < K; k0 += 32) {
        // batched loads before barrier (MLP=4)
        uint4 ra0 = *reinterpret_cast<const uint4*>(pA + k0);
        uint4 ra1 = *reinterpret_cast<const uint4*>(pA + k0 + 8);
        uint4 rb0 = *reinterpret_cast<const uint4*>(pB + k0);
        uint4 rb1 = *reinterpret_cast<const uint4*>(pB + k0 + 8);
        __syncthreads();
        *reinterpret_cast<uint4*>(&Ash[lrow * AS_LD + loff])     = ra0;
        *reinterpret_cast<uint4*>(&Ash[lrow * AS_LD + loff + 8]) = ra1;
        *reinterpret_cast<uint4*>(&Bsh[lrow * AS_LD + loff])     = rb0;
        *reinterpret_cast<uint4*>(&Bsh[lrow * AS_LD + loff + 8]) = rb1;
        __syncthreads();

        #pragma unroll
        for (int ks = 0; ks < 2; ks++) {
            uint32_t bh4[2][4];
            #pragma unroll
            for (int ntp = 0; ntp < 2; ntp++)
                ldm_x4(bh4[ntp], sBh + ntp * 1280 + ks * 32);
            #pragma unroll
            for (int mt = 0; mt < 4; mt++) {
                uint32_t ah4[4];
                ldm_x4(ah4, sAh + mt * 1280 + ks * 32);
                mma_f16(Cf[mt][0], ah4, &bh4[0][0]);
                mma_f16(Cf[mt][1], ah4, &bh4[0][2]);
                mma_f16(Cf[mt][2], ah4, &bh4[1][0]);
                mma_f16(Cf[mt][3], ah4, &bh4[1][2]);
            }
        }
    }

    #pragma unroll
    for (int mt = 0; mt < 4; mt++) {
        int row = m0 + wm * 64 + mt * 16 + g;
        #pragma unroll
        for (int nt = 0; nt < 4; nt++) {
            int col = n0 + wn * 32 + nt * 8 + 2 * q4;
            float2 b2 = *reinterpret_cast<const float2*>(bias + col);
            float o00 = Cf[mt][nt][0] + b2.x, o01 = Cf[mt][nt][1] + b2.y;
            float o10 = Cf[mt][nt][2] + b2.x, o11 = Cf[mt][nt][3] + b2.y;
            if (Ch) {
                *reinterpret_cast<uint32_t*>(Ch + (size_t)row * N + col) = h2pack(o00, o01);
                *reinterpret_cast<uint32_t*>(Ch + (size_t)(row + 8) * N + col) = h2pack(o10, o11);
            } else {
                float2 v0 = {o00, o01};
                float2 v1 = {o10, o11};
                *reinterpret_cast<float2*>(C + (size_t)row * N + col) = v0;
                *reinterpret_cast<float2*>(C + (size_t)(row + 8) * N + col) = v1;
            }
        }
    }
}

// ---------------------------------------------------------------------------
// Flash attention, fp16 single-pass HMMA + ldmatrix. Br=128, Bc=64.
// Loaders cover full tiles: Q 4 iters (128 rows); K/V two uint4/thread.
// ---------------------------------------------------------------------------
#define FLD 72
#define OQ 0
#define OK (128 * FLD)          // 9216
#define OV (OK + 64 * FLD)      // 13824
#define FLASH_SM_ELEMS (OV + 64 * FLD)   // 18432 halves = 36864 B (static)

__global__ void __launch_bounds__(256, 2)
flash_f16_kernel(const __half* __restrict__ qkv_h, __half* __restrict__ outp) {
    __shared__ __half smf[FLASH_SM_ELEMS];
    const uint32_t sb = smem_u32(smf);

    const int qb = (S_LEN / 128 - 1) - blockIdx.x;   // heavy tiles first
    const int h  = blockIdx.y;
    const int tid = threadIdx.x;
    const int wid = tid >> 5, lane = tid & 31;
    const int g = lane >> 2, q4 = lane & 3;
    const int qcol = h * HDIM;
    const float scale = 0.125f;

    const uint32_t qoff2 = (uint32_t)(((wid * 16) + ((lane >> 3) & 1) * 8 + (lane & 7)) * FLD
                                      + (lane >> 4) * 8) * 2;
    const uint32_t koff2 = (uint32_t)(((lane >> 4) * 8 + (lane & 7)) * FLD
                                      + ((lane >> 3) & 1) * 8) * 2;
    const uint32_t voff2 = (uint32_t)((((lane >> 3) & 1) * 8 + (lane & 7)) * FLD
                                      + (lane >> 4) * 8) * 2;

    // Q load: 128 rows x 8 uint4/row = 1024 uint4 -> 4 per thread
    #pragma unroll
    for (int i = 0; i < 4; i++) {
        int p = tid + i * 256;
        int r = p >> 3, c8 = (p & 7) * 8;
        *reinterpret_cast<uint4*>(&smf[OQ + r * FLD + c8]) =
            *reinterpret_cast<const uint4*>(qkv_h + (size_t)(qb * 128 + r) * N3 + qcol + c8);
    }

    float O[8][4];
    #pragma unroll
    for (int nt = 0; nt < 8; nt++)
        #pragma unroll
        for (int e = 0; e < 4; e++) O[nt][e] = 0.0f;
    float m0r = -1e30f, m1r = -1e30f, l0r = 0.0f, l1r = 0.0f;

    const uint32_t qbs = sb + OQ * 2 + qoff2;
    const uint32_t kbs = sb + OK * 2 + koff2;
    const uint32_t vbs = sb + OV * 2 + voff2;

    // K/V staging: 64 rows x 8 uint4 = 512 uint4 each -> 2 per thread each
    const int r0_ = tid >> 3, c80_ = (tid & 7) * 8;          // rows 0..31
    const int r1_ = (tid + 256) >> 3, c81_ = ((tid + 256) & 7) * 8;  // rows 32..63

    const int nkt = 2 * qb + 2;
    for (int kb = 0; kb < nkt; kb++) {
        size_t ks0 = (size_t)(kb * 64 + r0_) * N3 + DMODEL + qcol + c80_;
        size_t ks1 = (size_t)(kb * 64 + r1_) * N3 + DMODEL + qcol + c81_;
        uint4 kv0 = *reinterpret_cast<const uint4*>(qkv_h + ks0);
        uint4 vv0 = *reinterpret_cast<const uint4*>(qkv_h + ks0 + DMODEL);
        uint4 kv1 = *reinterpret_cast<const uint4*>(qkv_h + ks1);
        uint4 vv1 = *reinterpret_cast<const uint4*>(qkv_h + ks1 + DMODEL);
        __syncthreads();   // prior iter done reading K/V (covers Q stores on iter 0)
        *reinterpret_cast<uint4*>(&smf[OK + r0_ * FLD + c80_]) = kv0;
        *reinterpret_cast<uint4*>(&smf[OV + r0_ * FLD + c80_]) = vv0;
        *reinterpret_cast<uint4*>(&smf[OK + r1_ * FLD + c81_]) = kv1;
        *reinterpret_cast<uint4*>(&smf[OV + r1_ * FLD + c81_]) = vv1;
        __syncthreads();

        // ---- S = Q K^T (single-pass fp16) ----
        float S[8][4];
        #pragma unroll
        for (int nt = 0; nt < 8; nt++)
            #pragma unroll
            for (int e = 0; e < 4; e++) S[nt][e] = 0.0f;

        #pragma unroll
        for (int ks = 0; ks < 4; ks++) {
            uint32_t q4f[4];
            ldm_x4(q4f, qbs + ks * 32);
            #pragma unroll
            for (int ntp = 0; ntp < 4; ntp++) {
                uint32_t k4f[4];
                ldm_x4(k4f, kbs + ntp * 2304 + ks * 32);   // 16*FLD*2 = 2304
                mma_f16(S[2 * ntp],     q4f, &k4f[0]);
                mma_f16(S[2 * ntp + 1], q4f, &k4f[2]);
            }
        }

        // scale (fp32), causal mask
        #pragma unroll
        for (int nt = 0; nt < 8; nt++) {
            S[nt][0] *= scale; S[nt][1] *= scale;
            S[nt][2] *= scale; S[nt][3] *= scale;
        }
        if (kb >= 2 * qb) {
            int row0 = qb * 128 + wid * 16 + g;
            int row1 = row0 + 8;
            #pragma unroll
            for (int nt = 0; nt < 8; nt++) {
                int c = kb * 64 + nt * 8 + 2 * q4;
                if (c     > row0) S[nt][0] = -1e30f;
                if (c + 1 > row0) S[nt][1] = -1e30f;
                if (c     > row1) S[nt][2] = -1e30f;
                if (c + 1 > row1) S[nt][3] = -1e30f;
            }
        }

        // online softmax (quad reductions)
        float mx0 = -1e30f, mx1 = -1e30f;
        #pragma unroll
        for (int nt = 0; nt < 8; nt++) {
            mx0 = fmaxf(mx0, fmaxf(S[nt][0], S[nt][1]));
            mx1 = fmaxf(mx1, fmaxf(S[nt][2], S[nt][3]));
        }
        mx0 = fmaxf(mx0, __shfl_xor_sync(0xffffffffu, mx0, 1));
        mx0 = fmaxf(mx0, __shfl_xor_sync(0xffffffffu, mx0, 2));
        mx1 = fmaxf(mx1, __shfl_xor_sync(0xffffffffu, mx1, 1));
        mx1 = fmaxf(mx1, __shfl_xor_sync(0xffffffffu, mx1, 2));
        float mn0 = fmaxf(m0r, mx0), mn1 = fmaxf(m1r, mx1);
        float al0 = __expf(m0r - mn0), al1 = __expf(m1r - mn1);
        float rs0 = 0.0f, rs1 = 0.0f;
        #pragma unroll
        for (int nt = 0; nt < 8; nt++) {
            S[nt][0] = __expf(S[nt][0] - mn0);
            S[nt][1] = __expf(S[nt][1] - mn0);
            S[nt][2] = __expf(S[nt][2] - mn1);
            S[nt][3] = __expf(S[nt][3] - mn1);
            rs0 += S[nt][0] + S[nt][1];
            rs1 += S[nt][2] + S[nt][3];
        }
        rs0 += __shfl_xor_sync(0xffffffffu, rs0, 1);
        rs0 += __shfl_xor_sync(0xffffffffu, rs0, 2);
        rs1 += __shfl_xor_sync(0xffffffffu, rs1, 1);
        rs1 += __shfl_xor_sync(0xffffffffu, rs1, 2);
        l0r = l0r * al0 + rs0;
        l1r = l1r * al1 + rs1;
        m0r = mn0; m1r = mn1;
        #pragma unroll
        for (int nt = 0; nt < 8; nt++) {
            O[nt][0] *= al0; O[nt][1] *= al0;
            O[nt][2] *= al1; O[nt][3] *= al1;
        }

        // ---- O += P @ V (P packed fp16 from regs; V via ldmatrix.trans) ----
        #pragma unroll
        for (int ks = 0; ks < 4; ks++) {
            uint32_t ph[4];
            ph[0] = h2pack(S[2 * ks][0],     S[2 * ks][1]);
            ph[1] = h2pack(S[2 * ks][2],     S[2 * ks][3]);
            ph[2] = h2pack(S[2 * ks + 1][0], S[2 * ks + 1][1]);
            ph[3] = h2pack(S[2 * ks + 1][2], S[2 * ks + 1][3]);
            #pragma unroll
            for (int ntp = 0; ntp < 4; ntp++) {
                uint32_t v4f[4];
                ldm_x4_t(v4f, vbs + ks * 2304 + ntp * 32);
                mma_f16(O[2 * ntp],     ph, &v4f[0]);
                mma_f16(O[2 * ntp + 1], ph, &v4f[2]);
            }
        }
    }

    // epilogue: write fp16 attn
    float inv0 = 1.0f / l0r, inv1 = 1.0f / l1r;
    int row0 = qb * 128 + wid * 16 + g;
    int row1 = row0 + 8;
    #pragma unroll
    for (int nt = 0; nt < 8; nt++) {
        int col = qcol + nt * 8 + 2 * q4;
        *reinterpret_cast<uint32_t*>(outp + (size_t)row0 * DMODEL + col) =
            h2pack(O[nt][0] * inv0, O[nt][1] * inv0);
        *reinterpret_cast<uint32_t*>(outp + (size_t)row1 * DMODEL + col) =
            h2pack(O[nt][2] * inv1, O[nt][3] * inv1);
    }
}

// ---------------------------------------------------------------------------
// Launch
// ---------------------------------------------------------------------------
extern "C" void kernel_launch(void* const* d_in, const int* in_sizes, int n_in,
                              void* d_out, int out_size) {
    const float* x      = (const float*)d_in[0];
    const float* w_qkv  = (const float*)d_in[1];
    const float* b_qkv  = (const float*)d_in[2];
    const float* w_proj = (const float*)d_in[3];
    const float* b_proj = (const float*)d_in[4];
    float* out = (float*)d_out;

    __half *xh, *wqt, *wpt, *qkvh, *attnh;
    cudaGetSymbolAddress((void**)&xh, g_xh);
    cudaGetSymbolAddress((void**)&wqt, g_wqt);
    cudaGetSymbolAddress((void**)&wpt, g_wpt);
    cudaGetSymbolAddress((void**)&qkvh, g_qkvh);
    cudaGetSymbolAddress((void**)&attnh, g_attnh);

    // Prep: convert x; transpose+convert weights
    cvt_kernel<<<S_LEN * DMODEL / 1024, 256>>>(x, xh);
    transposeT_kernel<<<dim3(N3 / 32, DMODEL / 32), dim3(32, 8)>>>(w_qkv, wqt, DMODEL, N3);
    transposeT_kernel<<<dim3(DMODEL / 32, DMODEL / 32), dim3(32, 8)>>>(w_proj, wpt, DMODEL, DMODEL);

    // 1) QKV projection (fp16 HMMA, fp16 out with bias)
    gemm_f16_kernel<<<dim3(N3 / 128, S_LEN / 128), 256>>>(
        xh, wqt, b_qkv, nullptr, qkvh, S_LEN, N3, DMODEL);

    // 2) Causal flash attention (fp16 single-pass)
    flash_f16_kernel<<<dim3(S_LEN / 128, NHEAD), 256>>>(qkvh, attnh);

    // 3) Output projection (fp16 HMMA, fp32 out with bias)
    gemm_f16_kernel<<<dim3(DMODEL / 128, S_LEN / 128), 256>>>(
        attnh, wpt, b_proj, out, nullptr, S_LEN, DMODEL, DMODEL);
}